// round 4
// baseline (speedup 1.0000x reference)
#include <cuda_runtime.h>
#include <math.h>

#define BATCH 32
#define LDIM  4096
#define MEMD  256
#define NTURN 5
#define CPB   9                     // CTAs per batch in k_big
#define G_CTAS (BATCH * CPB)        // 288
#define ST_ROWS 16
#define ST_BYTES (ST_ROWS * MEMD * 4)   // 16384
#define NS 6
#define NSTG (LDIM / ST_ROWS)       // 256 stages per batch
#define BIG_SMEM (NS * ST_BYTES)    // 98304 B

// ---------------- device scratch ----------------
__device__ float g_s[BATCH * MEMD];
__device__ float g_qb[BATCH * MEMD];
__device__ float g_qa[BATCH * MEMD];
__device__ float g_qe[BATCH * MEMD];
__device__ float g_endvec[BATCH * MEMD];
__device__ float g_x1[BATCH * MEMD];
__device__ float g_scoreS[BATCH * LDIM];
__device__ float g_scoreE[BATCH * LDIM];
__device__ float g_pV1[G_CTAS * MEMD];
__device__ float g_pV2[G_CTAS * MEMD];
__device__ float g_pm1[G_CTAS], g_pz1[G_CTAS], g_pm2[G_CTAS], g_pz2[G_CTAS];

// ---------------- helpers ----------------
__device__ __forceinline__ unsigned smem_u32(const void* p) {
    return (unsigned)__cvta_generic_to_shared(p);
}
__device__ __forceinline__ void mbar_init(unsigned a, unsigned cnt) {
    asm volatile("mbarrier.init.shared.b64 [%0], %1;" :: "r"(a), "r"(cnt) : "memory");
}
__device__ __forceinline__ void mbar_expect_tx(unsigned a, unsigned bytes) {
    asm volatile("mbarrier.arrive.expect_tx.shared.b64 _, [%0], %1;" :: "r"(a), "r"(bytes) : "memory");
}
__device__ __forceinline__ void bulk_g2s(unsigned dst, const void* src, unsigned bytes, unsigned mbar) {
    asm volatile("cp.async.bulk.shared::cta.global.mbarrier::complete_tx::bytes [%0], [%1], %2, [%3];"
                 :: "r"(dst), "l"(src), "r"(bytes), "r"(mbar) : "memory");
}
__device__ __forceinline__ void mbar_wait(unsigned a, unsigned parity) {
    unsigned done;
    asm volatile("{\n\t.reg .pred p;\n\t"
                 "mbarrier.try_wait.parity.shared.b64 p, [%1], %2;\n\t"
                 "selp.b32 %0, 1, 0, p;\n\t}"
                 : "=r"(done) : "r"(a), "r"(parity) : "memory");
    if (!done) {
        asm volatile("{\n\t.reg .pred P1;\n\t"
                     "W_%=:\n\t"
                     "mbarrier.try_wait.parity.shared.b64 P1, [%0], %1, 0x989680;\n\t"
                     "@P1 bra.uni D_%=;\n\t"
                     "bra.uni W_%=;\n\t"
                     "D_%=:\n\t}"
                     :: "r"(a), "r"(parity) : "memory");
    }
}
__device__ __forceinline__ float dot44(float4 a, float4 x) {
    return a.x * x.x + a.y * x.y + a.z * x.z + a.w * x.w;
}
__device__ __forceinline__ void scale4(float4& v, float s) {
    v.x *= s; v.y *= s; v.z *= s; v.w *= s;
}
__device__ __forceinline__ void fma4(float4& v, float s, float4 x) {
    v.x += s * x.x; v.y += s * x.y; v.z += s * x.z; v.w += s * x.w;
}

// ---------------- init ----------------
__global__ void k_init(float* __restrict__ out, const float* __restrict__ s0, int outn) {
    int i = blockIdx.x * 256 + threadIdx.x;
    if (i < outn) out[i] = 0.0f;
    if (i < BATCH * MEMD) g_s[i] = s0[i];
}

// ---------------- dual vec-mat: qb = X@Wb^T, qa = X@Wa^T ----------------
__global__ void k_vm2(const float* __restrict__ X,
                      const float* __restrict__ Wb,
                      const float* __restrict__ Wa) {
    __shared__ float xs[BATCH * 257];
    const float* Xp = X ? X : g_s;
    int t = threadIdx.x;
    for (int i = t; i < BATCH * MEMD; i += 256)
        xs[(i >> 8) * 257 + (i & 255)] = Xp[i];
    __syncthreads();
    const float* W = blockIdx.y ? Wa : Wb;
    float* outv = blockIdx.y ? g_qa : g_qb;
    int w = t >> 5, lane = t & 31;
    int nbase = blockIdx.x * 64 + w * 8;
    const float* xrow = &xs[lane * 257];
    for (int r = 0; r < 8; r++) {
        int n = nbase + r;
        const float4* Wr = (const float4*)(W + n * 256);
        float acc = 0.0f;
        #pragma unroll 8
        for (int k4 = 0; k4 < 64; k4++) {
            float4 wv = __ldg(Wr + k4);
            int k = k4 * 4;
            acc += wv.x * xrow[k] + wv.y * xrow[k + 1] + wv.z * xrow[k + 2] + wv.w * xrow[k + 3];
        }
        outv[lane * MEMD + n] = acc;
    }
}

// ---------------- persistent big pass over M: bulk-copy pipeline ----------------
// grid G_CTAS (9 CTAs/batch), 256 threads, 2 CTAs/SM, NS=6 stages x 16 rows (16 KB).
// One cp.async.bulk per stage (issue-cost-free vs per-thread cp.async), up to 5
// stages (80 KB) in flight per CTA.
__global__ void __launch_bounds__(256, 2)
k_big(const float* __restrict__ M, int doMain, int doEnd) {
    extern __shared__ float sm[];                    // NS * 4096 floats (96 KB)
    __shared__ __align__(8) unsigned long long mfull[NS];
    __shared__ float cm1[8], cz1[8], cm2[8], cz2[8];

    const int b  = blockIdx.x / CPB;
    const int cb = blockIdx.x % CPB;
    const int g0 = (cb * NSTG) / CPB;
    const int g1 = ((cb + 1) * NSTG) / CPB;
    const int nst = g1 - g0;
    const int t = threadIdx.x, w = t >> 5, k = t & 31;

    if (t == 0) {
        #pragma unroll
        for (int i = 0; i < NS; i++) mbar_init(smem_u32(&mfull[i]), 1);
    }
    __syncthreads();

    // prefill all stages
    if (t == 0) {
        #pragma unroll
        for (int i = 0; i < NS; i++) {
            if (i < nst) {
                unsigned mb = smem_u32(&mfull[i]);
                mbar_expect_tx(mb, ST_BYTES);
                const float* src = M + ((size_t)b * LDIM + (size_t)(g0 + i) * ST_ROWS) * MEMD;
                bulk_g2s(smem_u32(sm + i * (ST_BYTES / 4)), src, ST_BYTES, mb);
            }
        }
    }

    float4 z4 = make_float4(0.f, 0.f, 0.f, 0.f);
    float4 qb0 = z4, qb1 = z4, qa0 = z4, qa1 = z4, qe0 = z4, qe1 = z4;
    const int bo = b * MEMD + 4 * k;
    if (doMain) {
        qb0 = *(const float4*)(g_qb + bo); qb1 = *(const float4*)(g_qb + bo + 128);
        qa0 = *(const float4*)(g_qa + bo); qa1 = *(const float4*)(g_qa + bo + 128);
    }
    if (doEnd) {
        qe0 = *(const float4*)(g_qe + bo); qe1 = *(const float4*)(g_qe + bo + 128);
    }

    float m1 = -1e30f, z1 = 0.f, m2 = -1e30f, z2 = 0.f;
    float4 V10 = z4, V11 = z4, V20 = z4, V21 = z4;

    for (int it = 0; it < nst; ++it) {
        const int st = it % NS;
        mbar_wait(smem_u32(&mfull[st]), (it / NS) & 1);

        const float4* tf = (const float4*)(sm + st * (ST_BYTES / 4));
        const int lbase = b * LDIM + (g0 + it) * ST_ROWS;

        #pragma unroll
        for (int r = 0; r < 2; r++) {
            int row = 2 * w + r;
            float4 x0  = tf[row * 64 + k];
            float4 x1v = tf[row * 64 + 32 + k];
            float db = 0.f, da = 0.f, de = 0.f;
            if (doMain) {
                db = dot44(qb0, x0) + dot44(qb1, x1v);
                da = dot44(qa0, x0) + dot44(qa1, x1v);
            }
            if (doEnd) de = dot44(qe0, x0) + dot44(qe1, x1v);
            #pragma unroll
            for (int off = 16; off; off >>= 1) {
                db += __shfl_xor_sync(~0u, db, off);
                da += __shfl_xor_sync(~0u, da, off);
                de += __shfl_xor_sync(~0u, de, off);
            }
            if (doMain) {
                if (db > m1) {
                    float sc = __expf(m1 - db);
                    z1 *= sc; scale4(V10, sc); scale4(V11, sc); m1 = db;
                }
                float w1 = __expf(db - m1);
                z1 += w1; fma4(V10, w1, x0); fma4(V11, w1, x1v);
                if (da > m2) {
                    float sc = __expf(m2 - da);
                    z2 *= sc; scale4(V20, sc); scale4(V21, sc); m2 = da;
                }
                float w2 = __expf(da - m2);
                z2 += w2; fma4(V20, w2, x0); fma4(V21, w2, x1v);
            }
            if (k == 0) {
                if (doMain) g_scoreS[lbase + row] = db;
                if (doEnd)  g_scoreE[lbase + row] = de;
            }
        }
        __syncthreads();   // all threads done reading stage st
        if (t == 0 && it + NS < nst) {
            unsigned mb = smem_u32(&mfull[st]);
            mbar_expect_tx(mb, ST_BYTES);
            const float* src = M + ((size_t)b * LDIM + (size_t)(g0 + it + NS) * ST_ROWS) * MEMD;
            bulk_g2s(smem_u32(sm + st * (ST_BYTES / 4)), src, ST_BYTES, mb);
        }
    }

    // ---- single CTA-combine; reuse stage smem for cV buffers ----
    if (doMain) {
        __syncthreads();
        float* cV1 = sm;
        float* cV2 = sm + 2048;
        *(float4*)(cV1 + w * MEMD + 4 * k)       = V10;
        *(float4*)(cV1 + w * MEMD + 128 + 4 * k) = V11;
        *(float4*)(cV2 + w * MEMD + 4 * k)       = V20;
        *(float4*)(cV2 + w * MEMD + 128 + 4 * k) = V21;
        if (k == 0) { cm1[w] = m1; cz1[w] = z1; cm2[w] = m2; cz2[w] = z2; }
        __syncthreads();
        float a1 = cm1[0], a2 = cm2[0];
        #pragma unroll
        for (int wi = 1; wi < 8; wi++) {
            a1 = fmaxf(a1, cm1[wi]); a2 = fmaxf(a2, cm2[wi]);
        }
        float v1 = 0.f, gz1 = 0.f, v2 = 0.f, gz2 = 0.f;
        #pragma unroll
        for (int wi = 0; wi < 8; wi++) {
            float e1 = __expf(cm1[wi] - a1), e2 = __expf(cm2[wi] - a2);
            v1 += e1 * cV1[wi * MEMD + t]; gz1 += e1 * cz1[wi];
            v2 += e2 * cV2[wi * MEMD + t]; gz2 += e2 * cz2[wi];
        }
        int slot = blockIdx.x;
        g_pV1[slot * MEMD + t] = v1;
        g_pV2[slot * MEMD + t] = v2;
        if (t == 0) {
            g_pm1[slot] = a1; g_pz1[slot] = gz1;
            g_pm2[slot] = a2; g_pz2[slot] = gz2;
        }
    }
}

// ---------------- softmax over stored scores, accumulate probs into out ----------------
__global__ void k_softmax_acc(float* __restrict__ out, int doStart, int doEnd) {
    int which = blockIdx.y;
    if (which == 0 ? !doStart : !doEnd) return;
    int b = blockIdx.x, t = threadIdx.x;
    const float* sc = (which ? g_scoreE : g_scoreS) + b * LDIM;
    float* o = out + (size_t)which * BATCH * LDIM + b * LDIM;

    float v[16];
    float lm = -1e30f;
    #pragma unroll
    for (int i = 0; i < 16; i++) { v[i] = sc[i * 256 + t]; lm = fmaxf(lm, v[i]); }

    __shared__ float red[8];
    __shared__ float bc[2];
    #pragma unroll
    for (int off = 16; off; off >>= 1) lm = fmaxf(lm, __shfl_xor_sync(~0u, lm, off));
    if ((t & 31) == 0) red[t >> 5] = lm;
    __syncthreads();
    if (t == 0) {
        float m = red[0];
        for (int i = 1; i < 8; i++) m = fmaxf(m, red[i]);
        bc[0] = m;
    }
    __syncthreads();
    float m = bc[0];
    float ls = 0.0f;
    #pragma unroll
    for (int i = 0; i < 16; i++) { v[i] = __expf(v[i] - m); ls += v[i]; }
    #pragma unroll
    for (int off = 16; off; off >>= 1) ls += __shfl_xor_sync(~0u, ls, off);
    __syncthreads();
    if ((t & 31) == 0) red[t >> 5] = ls;
    __syncthreads();
    if (t == 0) {
        float z = 0.0f;
        for (int i = 0; i < 8; i++) z += red[i];
        bc[1] = 1.0f / z;
    }
    __syncthreads();
    float invz = bc[1];
    #pragma unroll
    for (int i = 0; i < 16; i++) o[i * 256 + t] += v[i] * invz;
}

// ---------------- merge per-CTA partials -> end_vec, x1 ----------------
__global__ void k_reduce() {
    int b = blockIdx.x, j = threadIdx.x;
    int base = b * CPB;
    float mg1 = -1e30f, mg2 = -1e30f;
    #pragma unroll
    for (int c = 0; c < CPB; c++) {
        mg1 = fmaxf(mg1, g_pm1[base + c]);
        mg2 = fmaxf(mg2, g_pm2[base + c]);
    }
    float v1 = 0.f, z1 = 0.f, v2 = 0.f, z2 = 0.f;
    #pragma unroll
    for (int c = 0; c < CPB; c++) {
        int p = base + c;
        float e1 = __expf(g_pm1[p] - mg1);
        float e2 = __expf(g_pm2[p] - mg2);
        v1 += e1 * g_pV1[p * MEMD + j];
        z1 += e1 * g_pz1[p];
        v2 += e2 * g_pV2[p * MEMD + j];
        z2 += e2 * g_pz2[p];
    }
    g_endvec[b * MEMD + j] = v1 / z1;
    g_x1[b * MEMD + j] = v2 / z2;
}

// ---------------- per-turn tail: qe = [s|end_vec]@We^T, GRU step ----------------
__global__ void k_turn2(const float* __restrict__ We,
                        const float* __restrict__ W_ih,
                        const float* __restrict__ W_hh,
                        const float* __restrict__ b_ih,
                        const float* __restrict__ b_hh) {
    extern __shared__ float sm[];
    float* ss  = sm;                    // 32*257
    float* ev  = ss + 32 * 257;
    float* xx  = ev + 32 * 257;
    float* qeo = xx + 32 * 257;         // 32*33
    float* gio = qeo + 32 * 33;         // 96*33
    float* gho = gio + 96 * 33;         // 96*33

    int c = blockIdx.x, t = threadIdx.x;
    for (int i = t; i < BATCH * MEMD; i += 256) {
        int bb = i >> 8, kk = i & 255;
        ss[bb * 257 + kk] = g_s[i];
        ev[bb * 257 + kk] = g_endvec[i];
        xx[bb * 257 + kk] = g_x1[i];
    }
    __syncthreads();

    int w = t >> 5, lane = t & 31;
    const float* srow = &ss[lane * 257];
    const float* erow = &ev[lane * 257];
    const float* xrow = &xx[lane * 257];

    for (int R = w; R < 224; R += 8) {
        float acc;
        if (R < 32) {
            int n = c * 32 + R;
            const float4* Wr0 = (const float4*)(We + (size_t)n * 512);
            const float4* Wr1 = (const float4*)(We + (size_t)n * 512 + 256);
            acc = 0.0f;
            #pragma unroll 8
            for (int k4 = 0; k4 < 64; k4++) {
                float4 wv = __ldg(Wr0 + k4);
                int k = k4 * 4;
                acc += wv.x * srow[k] + wv.y * srow[k + 1] + wv.z * srow[k + 2] + wv.w * srow[k + 3];
            }
            #pragma unroll 8
            for (int k4 = 0; k4 < 64; k4++) {
                float4 wv = __ldg(Wr1 + k4);
                int k = k4 * 4;
                acc += wv.x * erow[k] + wv.y * erow[k + 1] + wv.z * erow[k + 2] + wv.w * erow[k + 3];
            }
            qeo[R * 33 + lane] = acc;
        } else if (R < 128) {
            int idx = R - 32;
            int g = (idx >> 5) * 256 + c * 32 + (idx & 31);
            const float4* Wr = (const float4*)(W_ih + (size_t)g * 256);
            acc = __ldg(b_ih + g);
            #pragma unroll 8
            for (int k4 = 0; k4 < 64; k4++) {
                float4 wv = __ldg(Wr + k4);
                int k = k4 * 4;
                acc += wv.x * xrow[k] + wv.y * xrow[k + 1] + wv.z * xrow[k + 2] + wv.w * xrow[k + 3];
            }
            gio[idx * 33 + lane] = acc;
        } else {
            int idx = R - 128;
            int g = (idx >> 5) * 256 + c * 32 + (idx & 31);
            const float4* Wr = (const float4*)(W_hh + (size_t)g * 256);
            acc = __ldg(b_hh + g);
            #pragma unroll 8
            for (int k4 = 0; k4 < 64; k4++) {
                float4 wv = __ldg(Wr + k4);
                int k = k4 * 4;
                acc += wv.x * srow[k] + wv.y * srow[k + 1] + wv.z * srow[k + 2] + wv.w * srow[k + 3];
            }
            gho[idx * 33 + lane] = acc;
        }
    }
    __syncthreads();

    for (int p = t; p < 1024; p += 256) {
        int bb = p >> 5, jl = p & 31;
        float gir = gio[jl * 33 + bb], giz = gio[(32 + jl) * 33 + bb], gin = gio[(64 + jl) * 33 + bb];
        float ghr = gho[jl * 33 + bb], ghz = gho[(32 + jl) * 33 + bb], ghn = gho[(64 + jl) * 33 + bb];
        float r = 1.0f / (1.0f + __expf(-(gir + ghr)));
        float z = 1.0f / (1.0f + __expf(-(giz + ghz)));
        float n = tanhf(gin + r * ghn);
        int col = c * 32 + jl;
        float sold = ss[bb * 257 + col];
        g_s[bb * MEMD + col] = (1.0f - z) * n + z * sold;
        g_qe[bb * MEMD + col] = qeo[jl * 33 + bb];
    }
}

// ---------------- finalize ----------------
__global__ void k_final(float* __restrict__ out, int n) {
    int i = blockIdx.x * 256 + threadIdx.x;
    if (i < n) out[i] = logf(out[i] * (1.0f / NTURN));
}

// ---------------- launch ----------------
extern "C" void kernel_launch(void* const* d_in, const int* in_sizes, int n_in,
                              void* d_out, int out_size) {
    (void)in_sizes; (void)n_in;
    const float* M    = (const float*)d_in[0];
    const float* s0   = (const float*)d_in[1];
    const float* Wb   = (const float*)d_in[2];
    const float* We   = (const float*)d_in[3];
    const float* Wa   = (const float*)d_in[4];
    const float* W_ih = (const float*)d_in[5];
    const float* W_hh = (const float*)d_in[6];
    const float* b_ih = (const float*)d_in[7];
    const float* b_hh = (const float*)d_in[8];
    float* out = (float*)d_out;

    const int T2_SMEM = (3 * 32 * 257 + 32 * 33 + 2 * 96 * 33) * 4;
    cudaFuncSetAttribute(k_big,   cudaFuncAttributeMaxDynamicSharedMemorySize, BIG_SMEM);
    cudaFuncSetAttribute(k_turn2, cudaFuncAttributeMaxDynamicSharedMemorySize, T2_SMEM);

    int gblocks = (out_size + 255) / 256;
    if (gblocks < 32) gblocks = 32;
    k_init<<<gblocks, 256>>>(out, s0, out_size);
    k_vm2<<<dim3(4, 2), 256>>>(s0, Wb, Wa);

    for (int tn = 0; tn < NTURN; tn++) {
        k_big<<<G_CTAS, 256, BIG_SMEM>>>(M, 1, tn > 0 ? 1 : 0);
        k_softmax_acc<<<dim3(BATCH, 2), 256>>>(out, 1, tn > 0 ? 1 : 0);
        k_reduce<<<BATCH, 256>>>();
        k_turn2<<<8, 256, T2_SMEM>>>(We, W_ih, W_hh, b_ih, b_hh);
        k_vm2<<<dim3(4, 2), 256>>>(nullptr, Wb, Wa);
    }
    k_big<<<G_CTAS, 256, BIG_SMEM>>>(M, 0, 1);
    k_softmax_acc<<<dim3(BATCH, 2), 256>>>(out, 0, 1);
    k_final<<<(out_size + 255) / 256, 256>>>(out, out_size);
}